// round 17
// baseline (speedup 1.0000x reference)
#include <cuda_runtime.h>

#define BB 128
#define NN 100
#define EE 3200
#define NT 768

typedef unsigned long long u64;

struct Args {
    const float* nodes;
    const int*   ei;
    const float* ea;
    const int*   agent;
    const float* emb;
    const float *W1,*b1,*W2,*b2,*W3,*b3,*lng,*lnb;
    const float *g1Wq,*g1bq,*g1Wk,*g1bk,*g1Wv,*g1bv,*g1We,*g1Ws,*g1bs;
    const float *g2Wq,*g2bq,*g2Wk,*g2bk,*g2Wv,*g2bv,*g2We,*g2Ws,*g2bs;
    float* out;
};

// block-private global scratch, indexed by CSR position p (sequential reads)
__device__ float g_hbuf [(size_t)BB * EE * 16];
__device__ float g_eabuf[(size_t)BB * EE * 8];

__device__ __forceinline__ u64 fma2(u64 a, u64 b, u64 c) {
    u64 d; asm("fma.rn.f32x2 %0,%1,%2,%3;" : "=l"(d) : "l"(a), "l"(b), "l"(c)); return d;
}
__device__ __forceinline__ u64 pk2(float lo, float hi) {
    u64 r; asm("mov.b64 %0,{%1,%2};" : "=l"(r) : "f"(lo), "f"(hi)); return r;
}
__device__ __forceinline__ float hadd2(u64 v) {
    float lo, hi; asm("mov.b64 {%0,%1},%2;" : "=f"(lo), "=f"(hi) : "l"(v)); return lo + hi;
}
__device__ __forceinline__ void unpk2(u64 v, float& lo, float& hi) {
    asm("mov.b64 {%0,%1},%2;" : "=f"(lo), "=f"(hi) : "l"(v));
}

__device__ __forceinline__ float fexp(float x) {
    float t = x * 1.4426950408889634f;
    float n = rintf(t);
    float f = t - n;
    float p = 1.3333558e-3f;
    p = p * f + 9.6181291e-3f;
    p = p * f + 5.5504109e-2f;
    p = p * f + 2.4022651e-1f;
    p = p * f + 6.9314718e-1f;
    p = p * f + 1.0f;
    int ni = (int)n;
    ni = max(-126, min(127, ni));
    return p * __int_as_float((ni + 127) << 23);
}

struct SM {
    float z[NN * 16];
    float q[NN * 66], k[NN * 66], v[NN * 66];
    float root1[NN * 16];
    float abuf[NN * 18];       // g1 output a (stride 18)
    float qwe[NN * 32];        // qWe for logits (needed nodes)
    float wes[128 * 9];        // We padded stride 9 (conflict-free per-u reads)
    float Mf[512];             // M[h][j][j'] = sum_c We[hc,j]*Wq[hc,j']
    float qweb[32];            // bias term sum_c We[hc,j]*bq[hc]
    float ct[80];              // etype-folded layer1 bias: ct[t*16+o]
    float4 W1v[48];  float b1[16];
    float4 W2v[64];  float b2[16];
    float4 W3v[64];  float b3[16];
    float lng[16], lnb[16], emb[20];
    float WqT[16 * 66], WkT[16 * 66], WvT[16 * 66];
    float g1bq[64], g1bk[64], g1bv[64];
    float4 Wev[128];
    float WsT[256];
    float g1bs[16];
    float qa[128], roota[32], denom2[4], acc2[128];
    int csr[EE];               // (dst<<19)|(src<<12)|e
    int rowptr[NN + 1];
    int cursor[NN], deg[NN], etype[NN];
    int needed[NN], slist[NN];
    int scount, agent;
};
static_assert(sizeof(SM) <= 232448, "smem over limit");

__device__ __forceinline__ void cpf(float* d, const float* s, int n, int tid) {
    for (int i = tid; i < n; i += NT) d[i] = s[i];
}

__device__ __forceinline__ void ln16(float* h, const float* g, const float* bb) {
    float m = 0.f;
#pragma unroll
    for (int i = 0; i < 16; i++) m += h[i];
    m *= (1.f / 16.f);
    float var = 0.f;
#pragma unroll
    for (int i = 0; i < 16; i++) { float d = h[i] - m; var += d * d; }
    var *= (1.f / 16.f);
    float inv = rsqrtf(var + 1e-5f);
#pragma unroll
    for (int i = 0; i < 16; i++) h[i] = (h[i] - m) * inv * g[i] + bb[i];
}

__global__ void __launch_bounds__(NT, 1) gnn_kernel(Args A) {
    extern __shared__ unsigned char smraw[];
    SM* s = reinterpret_cast<SM*>(smraw);
    const int b = blockIdx.x;
    const int tid = threadIdx.x;
    const int* ei = A.ei + b * 2 * EE;
    const float* eag = A.ea + (size_t)b * EE * 8;
    const float* wef = (const float*)s->Wev;
    float* hpos = g_hbuf + (size_t)b * EE * 16;
    float* epos = g_eabuf + (size_t)b * EE * 8;

    // ---- S0 ----
    cpf((float*)s->W1v, A.W1, 192, tid);  cpf(s->b1, A.b1, 16, tid);
    cpf((float*)s->W2v, A.W2, 256, tid);  cpf(s->b2, A.b2, 16, tid);
    cpf((float*)s->W3v, A.W3, 256, tid);  cpf(s->b3, A.b3, 16, tid);
    cpf(s->lng, A.lng, 16, tid); cpf(s->lnb, A.lnb, 16, tid);
    cpf(s->emb, A.emb, 20, tid);
    cpf((float*)s->Wev, A.g1We, 512, tid);
    cpf(s->g1bq, A.g1bq, 64, tid); cpf(s->g1bk, A.g1bk, 64, tid);
    cpf(s->g1bv, A.g1bv, 64, tid); cpf(s->g1bs, A.g1bs, 16, tid);
    for (int i = tid; i < 1024; i += NT) {
        const int u = i >> 4, j = i & 15;
        s->WqT[j * 66 + u] = A.g1Wq[i];
        s->WkT[j * 66 + u] = A.g1Wk[i];
        s->WvT[j * 66 + u] = A.g1Wv[i];
    }
    for (int i = tid; i < 1024; i += NT) {
        const int u = i >> 3, j = i & 7;
        s->wes[u * 9 + j] = A.g1We[i];
    }
    for (int i = tid; i < 256; i += NT) {
        const int o = i >> 4, j = i & 15;
        s->WsT[j * 16 + o] = A.g1Ws[i];
    }
    for (int i = tid; i < NN; i += NT) {
        s->etype[i] = (int)A.nodes[b * NN + i];
        s->deg[i] = 0;
        s->needed[i] = 0;
    }
    for (int i = tid; i < 4; i += NT) s->denom2[i] = 0.f;
    for (int i = tid; i < 128; i += NT) s->acc2[i] = 0.f;
    if (tid == 0) { s->agent = A.agent[b]; s->scount = 0; }
    __syncthreads();

    const int ag = s->agent;

    // ---- S0b: histogram + needed marking + M/qweb/ct precompute ----
    if (tid == 0) s->needed[ag] = 1;
    for (int e = tid; e < EE; e += NT) {
        const int dst = ei[EE + e];
        atomicAdd(&s->deg[dst], 1);
        if (dst == ag) s->needed[ei[e]] = 1;
    }
    for (int i = tid; i < 512; i += NT) {
        const int h = i >> 7, j = (i >> 4) & 7, jp = i & 15;
        float acc = 0.f;
#pragma unroll
        for (int c = 0; c < 16; c++)
            acc += wef[(h * 16 + c) * 8 + j] * s->WqT[jp * 66 + h * 16 + c];
        s->Mf[i] = acc;
    }
    for (int i = tid; i < 32; i += NT) {
        const int h = i >> 3, j = i & 7;
        float acc = 0.f;
#pragma unroll
        for (int c = 0; c < 16; c++)
            acc += wef[(h * 16 + c) * 8 + j] * s->g1bq[h * 16 + c];
        s->qweb[i] = acc;
    }
    // ct[t*16+o] = b1[o] + W1[o,0:4] . emb[t]
    for (int i = tid; i < 80; i += NT) {
        const int t = i >> 4, o = i & 15;
        const float4 w0 = s->W1v[o * 3];
        const float4 em = *(const float4*)&s->emb[t * 4];
        s->ct[i] = s->b1[o] + w0.x * em.x + w0.y * em.y + w0.z * em.z + w0.w * em.w;
    }
    __syncthreads();

    // ---- S0c: warp-parallel prefix sum + slist ----
    if (tid < 32) {
        int d0[4]; int t = 0;
#pragma unroll
        for (int u = 0; u < 4; u++) {
            const int n = tid * 4 + u;
            d0[u] = (n < NN) ? s->deg[n] : 0;
            t += d0[u];
        }
        int incl = t;
#pragma unroll
        for (int o = 1; o < 32; o <<= 1) {
            const int vv = __shfl_up_sync(0xFFFFFFFFu, incl, o);
            if (tid >= o) incl += vv;
        }
        int run = incl - t;
#pragma unroll
        for (int u = 0; u < 4; u++) {
            const int n = tid * 4 + u;
            if (n < NN) { s->rowptr[n] = run; run += d0[u]; }
        }
        if (tid == 31) s->rowptr[NN] = incl;
    }
    for (int n = tid; n < NN; n += NT)
        if (s->needed[n]) { const int si = atomicAdd(&s->scount, 1); s->slist[si] = n; }
    __syncthreads();
    for (int n = tid; n < NN; n += NT) s->cursor[n] = s->rowptr[n];
    __syncthreads();

    // ---- S1a: CSR scatter + per-edge MLP (etype-folded L1); by POSITION ----
    for (int e = tid; e < EE; e += NT) {
        const int src = ei[e], dst = ei[EE + e];
        const int pos = atomicAdd(&s->cursor[dst], 1);
        s->csr[pos] = (dst << 19) | (src << 12) | e;

        const int t = s->etype[src];
        const float4 xB = *(const float4*)(eag + (size_t)e * 8);
        const float4 xC = *(const float4*)(eag + (size_t)e * 8 + 4);

        float4* ep = (float4*)&epos[(size_t)pos * 8];
        ep[0] = xB; ep[1] = xC;

        u64 xp[4];
        xp[0] = pk2(xB.x, xB.y); xp[1] = pk2(xB.z, xB.w);
        xp[2] = pk2(xC.x, xC.y); xp[3] = pk2(xC.z, xC.w);
        const float* ctr = &s->ct[t * 16];

        float h[16], h2[16];
#pragma unroll
        for (int o = 0; o < 16; o++) {
            const ulonglong2* wr = reinterpret_cast<const ulonglong2*>(&s->W1v[o * 3]);
            const ulonglong2 wb = wr[1], wc = wr[2];
            u64 acc = pk2(ctr[o], 0.f);
            acc = fma2(wb.x, xp[0], acc); acc = fma2(wb.y, xp[1], acc);
            acc = fma2(wc.x, xp[2], acc); acc = fma2(wc.y, xp[3], acc);
            h[o] = fmaxf(hadd2(acc), 0.f);
        }
        ln16(h, s->lng, s->lnb);
        u64 hp2[8];
#pragma unroll
        for (int i = 0; i < 8; i++) hp2[i] = pk2(h[i * 2], h[i * 2 + 1]);
#pragma unroll
        for (int o = 0; o < 16; o++) {
            const ulonglong2* wr = reinterpret_cast<const ulonglong2*>(&s->W2v[o * 4]);
            const ulonglong2 w0 = wr[0], w1 = wr[1], w2 = wr[2], w3 = wr[3];
            u64 acc = pk2(s->b2[o], 0.f);
            acc = fma2(w0.x, hp2[0], acc); acc = fma2(w0.y, hp2[1], acc);
            acc = fma2(w1.x, hp2[2], acc); acc = fma2(w1.y, hp2[3], acc);
            acc = fma2(w2.x, hp2[4], acc); acc = fma2(w2.y, hp2[5], acc);
            acc = fma2(w3.x, hp2[6], acc); acc = fma2(w3.y, hp2[7], acc);
            h2[o] = fmaxf(hadd2(acc), 0.f);
        }
        ln16(h2, s->lng, s->lnb);
#pragma unroll
        for (int i = 0; i < 8; i++) hp2[i] = pk2(h2[i * 2], h2[i * 2 + 1]);
#pragma unroll
        for (int o = 0; o < 16; o++) {
            const ulonglong2* wr = reinterpret_cast<const ulonglong2*>(&s->W3v[o * 4]);
            const ulonglong2 w0 = wr[0], w1 = wr[1], w2 = wr[2], w3 = wr[3];
            u64 acc = pk2(s->b3[o], 0.f);
            acc = fma2(w0.x, hp2[0], acc); acc = fma2(w0.y, hp2[1], acc);
            acc = fma2(w1.x, hp2[2], acc); acc = fma2(w1.y, hp2[3], acc);
            acc = fma2(w2.x, hp2[4], acc); acc = fma2(w2.y, hp2[5], acc);
            acc = fma2(w3.x, hp2[6], acc); acc = fma2(w3.y, hp2[7], acc);
            h[o] = fmaxf(hadd2(acc), 0.f);
        }
        ln16(h, s->lng, s->lnb);

        float4* hp = (float4*)&hpos[(size_t)pos * 16];
        hp[0] = make_float4(h[0], h[1], h[2], h[3]);
        hp[1] = make_float4(h[4], h[5], h[6], h[7]);
        hp[2] = make_float4(h[8], h[9], h[10], h[11]);
        hp[3] = make_float4(h[12], h[13], h[14], h[15]);
    }
    __syncthreads();

    // ---- S1b: z gather — sequential by position, parity split ----
    for (int idx = tid; idx < NN * 8; idx += NT) {
        const int par = idx & 1, g = (idx >> 1) & 3, n = idx >> 3;
        const int p1 = s->rowptr[n + 1];
        float4 acc = make_float4(0.f, 0.f, 0.f, 0.f);
        for (int p = s->rowptr[n] + par; p < p1; p += 2) {
            const float4 hv = *(const float4*)&hpos[(size_t)p * 16 + g * 4];
            acc.x += hv.x; acc.y += hv.y; acc.z += hv.z; acc.w += hv.w;
        }
        acc.x += __shfl_xor_sync(0xFFFFFFFFu, acc.x, 1);
        acc.y += __shfl_xor_sync(0xFFFFFFFFu, acc.y, 1);
        acc.z += __shfl_xor_sync(0xFFFFFFFFu, acc.z, 1);
        acc.w += __shfl_xor_sync(0xFFFFFFFFu, acc.w, 1);
        if (!par) *(float4*)&s->z[n * 16 + g * 4] = acc;
    }
    __syncthreads();

    const int sc = s->scount;

    // ---- S2 region: k,v all; q + root + qwe (via Mf) for needed nodes ----
    for (int idx = tid; idx < NN * 32; idx += NT) {
        const int n = idx >> 5, up = idx & 31;
        const int u = up * 2;
        const float* zr = &s->z[n * 16];
        u64 ak = *(const u64*)&s->g1bk[u];
        u64 av = *(const u64*)&s->g1bv[u];
#pragma unroll
        for (int j = 0; j < 16; j++) {
            const u64 zj = pk2(zr[j], zr[j]);
            ak = fma2(*(const u64*)&s->WkT[j * 66 + u], zj, ak);
            av = fma2(*(const u64*)&s->WvT[j * 66 + u], zj, av);
        }
        *(u64*)&s->k[n * 66 + u] = ak;
        *(u64*)&s->v[n * 66 + u] = av;
    }
    for (int idx = tid; idx < sc * 32; idx += NT) {
        const int si = idx >> 5, up = idx & 31;
        const int n = s->slist[si];
        const int u = up * 2;
        const float* zr = &s->z[n * 16];
        u64 aq = *(const u64*)&s->g1bq[u];
#pragma unroll
        for (int j = 0; j < 16; j++) {
            const u64 zj = pk2(zr[j], zr[j]);
            aq = fma2(*(const u64*)&s->WqT[j * 66 + u], zj, aq);
        }
        *(u64*)&s->q[n * 66 + u] = aq;
    }
    for (int idx = tid; idx < sc * 16; idx += NT) {
        const int si = idx >> 4, o = idx & 15;
        const int n = s->slist[si];
        float ac = s->g1bs[o];
#pragma unroll
        for (int j = 0; j < 16; j++) ac += s->WsT[j * 16 + o] * s->z[n * 16 + j];
        s->root1[n * 16 + o] = ac;
    }
    for (int idx = tid; idx < sc * 32; idx += NT) {
        const int si = idx >> 5, r = idx & 31;
        const int n = s->slist[si];
        const float* Mr = &s->Mf[r * 16];
        const float* zr = &s->z[n * 16];
        float acc = s->qweb[r];
#pragma unroll
        for (int jp = 0; jp < 16; jp++) acc += Mr[jp] * zr[jp];
        s->qwe[n * 32 + r] = acc;
    }
    __syncthreads();

    // ---- S3f: FUSED logits + wea/denom/message/finalize — warp per node ----
    {
        const int w = tid >> 5, l = tid & 31;
        const int jL = l & 7;
        const int base = l & 24;
        for (int si = w; si < sc; si += NT / 32) {
            const int n = s->slist[si];
            const int p0 = s->rowptr[n], p1 = s->rowptr[n + 1];
            const u64 qL = *(const u64*)&s->q[n * 66 + 2 * l];
            const float qweL = s->qwe[n * 32 + l];
            u64 accv = 0ull;
            float weaL = 0.f, dL = 0.f;
            for (int p = p0; p < p1; p++) {
                const int pk = s->csr[p];
                const int src = (pk >> 12) & 0x7F;
                const u64 kp = *(const u64*)&s->k[src * 66 + 2 * l];
                const float eaj = epos[(size_t)p * 8 + jL];
                float part = hadd2(fma2(qL, kp, 0ull)) + qweL * eaj;
                part += __shfl_xor_sync(0xFFFFFFFFu, part, 1);
                part += __shfl_xor_sync(0xFFFFFFFFu, part, 2);
                part += __shfl_xor_sync(0xFFFFFFFFu, part, 4);
                const float ex = fexp(part * 0.25f);
                accv = fma2(*(const u64*)&s->v[src * 66 + 2 * l], pk2(ex, ex), accv);
                weaL += ex * eaj;
                dL += ex;
            }
            float add0 = 0.f, add1 = 0.f;
#pragma unroll
            for (int j = 0; j < 8; j++) {
                const float wj = __shfl_sync(0xFFFFFFFFu, weaL, base | j);
                add0 += s->wes[(2 * l) * 9 + j] * wj;
                add1 += s->wes[(2 * l + 1) * 9 + j] * wj;
            }
            float a0, a1;
            unpk2(accv, a0, a1);
            const float inv = 1.f / (dL + 1e-16f);
            float r0 = (a0 + add0) * inv;
            float r1 = (a1 + add1) * inv;
            r0 += __shfl_xor_sync(0xFFFFFFFFu, r0, 8);
            r0 += __shfl_xor_sync(0xFFFFFFFFu, r0, 16);
            r1 += __shfl_xor_sync(0xFFFFFFFFu, r1, 8);
            r1 += __shfl_xor_sync(0xFFFFFFFFu, r1, 16);
            if (l < 8) {
                s->abuf[n * 18 + 2 * l]     = 0.25f * r0 + s->root1[n * 16 + 2 * l];
                s->abuf[n * 18 + 2 * l + 1] = 0.25f * r1 + s->root1[n * 16 + 2 * l + 1];
            }
        }
    }
    __syncthreads();

    // ---- S5: g2 agent q and root ----
    {
        const float* ar = &s->abuf[ag * 18];
        for (int u = tid; u < 128; u += NT) {
            float ac = A.g2bq[u];
#pragma unroll
            for (int j = 0; j < 16; j++) ac += A.g2Wq[u * 16 + j] * ar[j];
            s->qa[u] = ac;
        }
        for (int c = tid; c < 32; c += NT) {
            float ac = A.g2bs[c];
#pragma unroll
            for (int j = 0; j < 16; j++) ac += A.g2Ws[c * 16 + j] * ar[j];
            s->roota[c] = ac;
        }
    }
    __syncthreads();

    // ---- S6: g2 edges with dst == agent (ea by position) ----
    {
        const int p0 = s->rowptr[ag];
        const int m = s->rowptr[ag + 1] - p0;
        for (int w = tid; w < m * 4; w += NT) {
            const int pe = w >> 2, hh = w & 3;
            const int pk = s->csr[p0 + pe];
            const int src = (pk >> 12) & 0x7F;
            const float* eap = &epos[(size_t)(p0 + pe) * 8];
            float ear[8];
#pragma unroll
            for (int j = 0; j < 8; j++) ear[j] = eap[j];
            const float* ar = &s->abuf[src * 18];
            float ev[32];
            float lg = 0.f;
#pragma unroll
            for (int c = 0; c < 32; c++) {
                const int u = hh * 32 + c;
                float evv = 0.f;
#pragma unroll
                for (int j = 0; j < 8; j++) evv += A.g2We[u * 8 + j] * ear[j];
                ev[c] = evv;
                float kk = A.g2bk[u];
#pragma unroll
                for (int j = 0; j < 16; j++) kk += A.g2Wk[u * 16 + j] * ar[j];
                lg += s->qa[u] * (kk + evv);
            }
            const float ex = fexp(lg * 0.17677669529663689f);
            atomicAdd(&s->denom2[hh], ex);
#pragma unroll
            for (int c = 0; c < 32; c++) {
                const int u = hh * 32 + c;
                float vv = A.g2bv[u];
#pragma unroll
                for (int j = 0; j < 16; j++) vv += A.g2Wv[u * 16 + j] * ar[j];
                atomicAdd(&s->acc2[u], ex * (vv + ev[c]));
            }
        }
    }
    __syncthreads();

    // ---- S7: output at agent node ----
    for (int c = tid; c < 32; c += NT) {
        float sum = 0.f;
#pragma unroll
        for (int hh = 0; hh < 4; hh++)
            sum += s->acc2[hh * 32 + c] / (s->denom2[hh] + 1e-16f);
        A.out[b * 32 + c] = fmaxf(0.25f * sum + s->roota[c], 0.f);
    }
}

extern "C" void kernel_launch(void* const* d_in, const int* in_sizes, int n_in,
                              void* d_out, int out_size) {
    Args A;
    A.nodes = (const float*)d_in[0];
    A.ei    = (const int*)  d_in[1];
    A.ea    = (const float*)d_in[2];
    A.agent = (const int*)  d_in[3];
    A.emb   = (const float*)d_in[4];
    A.W1 = (const float*)d_in[5];  A.b1 = (const float*)d_in[6];
    A.W2 = (const float*)d_in[7];  A.b2 = (const float*)d_in[8];
    A.W3 = (const float*)d_in[9];  A.b3 = (const float*)d_in[10];
    A.lng = (const float*)d_in[11]; A.lnb = (const float*)d_in[12];
    A.g1Wq = (const float*)d_in[13]; A.g1bq = (const float*)d_in[14];
    A.g1Wk = (const float*)d_in[15]; A.g1bk = (const float*)d_in[16];
    A.g1Wv = (const float*)d_in[17]; A.g1bv = (const float*)d_in[18];
    A.g1We = (const float*)d_in[19];
    A.g1Ws = (const float*)d_in[20]; A.g1bs = (const float*)d_in[21];
    A.g2Wq = (const float*)d_in[22]; A.g2bq = (const float*)d_in[23];
    A.g2Wk = (const float*)d_in[24]; A.g2bk = (const float*)d_in[25];
    A.g2Wv = (const float*)d_in[26]; A.g2bv = (const float*)d_in[27];
    A.g2We = (const float*)d_in[28];
    A.g2Ws = (const float*)d_in[29]; A.g2bs = (const float*)d_in[30];
    A.out = (float*)d_out;

    cudaFuncSetAttribute(gnn_kernel, cudaFuncAttributeMaxDynamicSharedMemorySize,
                         (int)sizeof(SM));
    gnn_kernel<<<BB, NT, sizeof(SM)>>>(A);
}